// round 9
// baseline (speedup 1.0000x reference)
#include <cuda_runtime.h>
#include <cstdint>

// Problem constants (match reference generator)
#define BB    8            // batch
#define HH    32
#define WW    32
#define TT    4
#define BSs   3
#define DD    768
#define CELL_F4 ((BSs*DD)/4)   // 576 float4 per cell (2304 floats)
#define THREADS 192            // 3 float4 per thread per patch

// Store one patch payload (held in v0..v2) to the cells it covers.
__device__ __forceinline__
void store_patch(float4* __restrict__ out, int b, int y, int x, int s, int t,
                 int tix, const float4& v0, const float4& v1, const float4& v2) {
    const size_t cell0 = (((size_t)b * HH + y) * WW + x) * TT + t;
    float4* dst0 = out + cell0 * CELL_F4 + tix;
    if (s == 1) {
        __stcs(dst0,               v0);
        __stcs(dst0 + THREADS,     v1);
        __stcs(dst0 + 2 * THREADS, v2);
    } else {
        const size_t dX = (size_t)TT * CELL_F4;        // +1 in x
        const size_t dY = (size_t)WW * TT * CELL_F4;   // +1 in y
        float4* d00 = dst0;
        float4* d01 = dst0 + dX;
        float4* d10 = dst0 + dY;
        float4* d11 = dst0 + dY + dX;
        __stcs(d00,               v0);
        __stcs(d01,               v0);
        __stcs(d10,               v0);
        __stcs(d11,               v0);
        __stcs(d00 + THREADS,     v1);
        __stcs(d01 + THREADS,     v1);
        __stcs(d10 + THREADS,     v1);
        __stcs(d11 + THREADS,     v1);
        __stcs(d00 + 2 * THREADS, v2);
        __stcs(d01 + 2 * THREADS, v2);
        __stcs(d10 + 2 * THREADS, v2);
        __stcs(d11 + 2 * THREADS, v2);
    }
}

// Two patches per block: all 6 payload LDG.128 (two independent streams) are
// issued before any store. Block turnover supplies cross-block MLP.
// launch_bounds raised to 8 blocks/SM: at regs=40, 192*40*8 = 61440 <= 64K,
// so the previous (.,7) bound — not the RF — was what capped occupancy at 65%.
// The position tiling partitions the grid, so every output cell is written
// exactly once per launch (deterministic across graph replays).
__global__ __launch_bounds__(THREADS, 8)
void apt_expand_kernel(const float4* __restrict__ tok,
                       const int*    __restrict__ positions,
                       float4*       __restrict__ out,
                       int P) {
    const int i0 = blockIdx.x * 2;         // first patch of this block's pair
    const int i1 = i0 + 1;
    const int tix = threadIdx.x;

    // Both position loads first
    const int4 ra = __ldg((const int4*)(positions + (size_t)i0 * 4));
    const int4 rb = __ldg((const int4*)(positions + (size_t)i1 * 4));

    // Front-batch all 6 payload loads (coalesced, streaming: no reuse)
    const float4* srcA = tok + (size_t)i0 * CELL_F4;
    const float4* srcB = tok + (size_t)i1 * CELL_F4;
    const float4 a0 = __ldcs(&srcA[tix]);
    const float4 a1 = __ldcs(&srcA[tix + THREADS]);
    const float4 a2 = __ldcs(&srcA[tix + 2 * THREADS]);
    const float4 b0 = __ldcs(&srcB[tix]);
    const float4 b1 = __ldcs(&srcB[tix + THREADS]);
    const float4 b2 = __ldcs(&srcB[tix + 2 * THREADS]);

    const int bA = i0 / P;
    const int bB = i1 / P;

    store_patch(out, bA, ra.x, ra.y, ra.z, ra.w, tix, a0, a1, a2);
    store_patch(out, bB, rb.x, rb.y, rb.z, rb.w, tix, b0, b1, b2);
}

extern "C" void kernel_launch(void* const* d_in, const int* in_sizes, int n_in,
                              void* d_out, int out_size) {
    const float4* tok = (const float4*)d_in[0];     // modality_tokens [B, P*BS, D] fp32
    const int*    pos = (const int*)d_in[1];        // positions [B, P, 4] int32

    int P  = in_sizes[1] / (BB * 4);                // 2560
    int BP = BB * P;                                // 20480 patches (even)

    apt_expand_kernel<<<BP / 2, THREADS>>>(tok, pos, (float4*)d_out, P);
}

// round 11
// speedup vs baseline: 1.0117x; 1.0117x over previous
#include <cuda_runtime.h>
#include <cstdint>

// Problem constants (match reference generator)
#define BB    8            // batch
#define HH    32
#define WW    32
#define TT    4
#define BSs   3
#define DD    768
#define CELL_F4 ((BSs*DD)/4)   // 576 float4 per cell (2304 floats)
#define THREADS 192            // 3 float4 per thread per patch

// Store one patch payload (held in v0..v2) to the cells it covers.
__device__ __forceinline__
void store_patch(float4* __restrict__ out, int b, int y, int x, int s, int t,
                 int tix, const float4& v0, const float4& v1, const float4& v2) {
    const size_t cell0 = (((size_t)b * HH + y) * WW + x) * TT + t;
    float4* dst0 = out + cell0 * CELL_F4 + tix;
    if (s == 1) {
        // Fine patch (80% of patches): single cell, straight-line stores
        __stcs(dst0,               v0);
        __stcs(dst0 + THREADS,     v1);
        __stcs(dst0 + 2 * THREADS, v2);
    } else {
        // Coarse 2x2 patch: 4 cells at constant offsets, all 12 stores ILP'd
        const size_t dX = (size_t)TT * CELL_F4;        // +1 in x
        const size_t dY = (size_t)WW * TT * CELL_F4;   // +1 in y
        float4* d00 = dst0;
        float4* d01 = dst0 + dX;
        float4* d10 = dst0 + dY;
        float4* d11 = dst0 + dY + dX;
        __stcs(d00,               v0);
        __stcs(d01,               v0);
        __stcs(d10,               v0);
        __stcs(d11,               v0);
        __stcs(d00 + THREADS,     v1);
        __stcs(d01 + THREADS,     v1);
        __stcs(d10 + THREADS,     v1);
        __stcs(d11 + THREADS,     v1);
        __stcs(d00 + 2 * THREADS, v2);
        __stcs(d01 + 2 * THREADS, v2);
        __stcs(d10 + 2 * THREADS, v2);
        __stcs(d11 + 2 * THREADS, v2);
    }
}

// Two patches per block: all 6 payload LDG.128 (two independent streams) are
// issued before any store (front-batched MLP); block turnover supplies
// cross-block MLP. The kernel runs at the B300 LTS/HBM path cap
// (~7.0 TB/s effective on 491 MB mandatory traffic) — measured invariant
// across occupancy 62-83%, 1-vs-2 patches/block, and cache-hint variants.
// The position tiling partitions the grid, so every output cell is written
// exactly once per launch (deterministic across graph replays).
__global__ __launch_bounds__(THREADS, 7)
void apt_expand_kernel(const float4* __restrict__ tok,
                       const int*    __restrict__ positions,
                       float4*       __restrict__ out,
                       int P) {
    const int i0 = blockIdx.x * 2;         // first patch of this block's pair
    const int i1 = i0 + 1;
    const int tix = threadIdx.x;

    // Both position loads first
    const int4 ra = __ldg((const int4*)(positions + (size_t)i0 * 4));
    const int4 rb = __ldg((const int4*)(positions + (size_t)i1 * 4));

    // Front-batch all 6 payload loads (coalesced, streaming: no reuse)
    const float4* srcA = tok + (size_t)i0 * CELL_F4;
    const float4* srcB = tok + (size_t)i1 * CELL_F4;
    const float4 a0 = __ldcs(&srcA[tix]);
    const float4 a1 = __ldcs(&srcA[tix + THREADS]);
    const float4 a2 = __ldcs(&srcA[tix + 2 * THREADS]);
    const float4 b0 = __ldcs(&srcB[tix]);
    const float4 b1 = __ldcs(&srcB[tix + THREADS]);
    const float4 b2 = __ldcs(&srcB[tix + 2 * THREADS]);

    const int bA = i0 / P;
    const int bB = i1 / P;

    store_patch(out, bA, ra.x, ra.y, ra.z, ra.w, tix, a0, a1, a2);
    store_patch(out, bB, rb.x, rb.y, rb.z, rb.w, tix, b0, b1, b2);
}

extern "C" void kernel_launch(void* const* d_in, const int* in_sizes, int n_in,
                              void* d_out, int out_size) {
    const float4* tok = (const float4*)d_in[0];     // modality_tokens [B, P*BS, D] fp32
    const int*    pos = (const int*)d_in[1];        // positions [B, P, 4] int32

    int P  = in_sizes[1] / (BB * 4);                // 2560
    int BP = BB * P;                                // 20480 patches (even)

    apt_expand_kernel<<<BP / 2, THREADS>>>(tok, pos, (float4*)d_out, P);
}

// round 12
// speedup vs baseline: 1.0164x; 1.0046x over previous
#include <cuda_runtime.h>
#include <cstdint>

// Problem constants (match reference generator)
#define BB    8            // batch
#define HH    32
#define WW    32
#define TT    4
#define BSs   3
#define DD    768
#define CELL_F   (BSs*DD)        // 2304 floats per cell
#define CELL_C   (CELL_F/8)      // 288 32-byte chunks per cell
#define THREADS  192

// 256-bit global load/store (Blackwell LDG.E.256 / STG.E.256), streaming.
__device__ __forceinline__ void ldg256_cs(const float* p, float4& lo, float4& hi) {
    asm volatile("ld.global.cs.v8.f32 {%0,%1,%2,%3,%4,%5,%6,%7}, [%8];"
        : "=f"(lo.x), "=f"(lo.y), "=f"(lo.z), "=f"(lo.w),
          "=f"(hi.x), "=f"(hi.y), "=f"(hi.z), "=f"(hi.w)
        : "l"(p));
}
__device__ __forceinline__ void stg256_cs(float* p, const float4& lo, const float4& hi) {
    asm volatile("st.global.cs.v8.f32 [%0], {%1,%2,%3,%4,%5,%6,%7,%8};"
        :: "l"(p),
           "f"(lo.x), "f"(lo.y), "f"(lo.z), "f"(lo.w),
           "f"(hi.x), "f"(hi.y), "f"(hi.z), "f"(hi.w)
        : "memory");
}

// Store one 32B chunk (local chunk index lc within the patch payload) to every
// cell the patch covers (s is 1 or 2).
__device__ __forceinline__
void store_chunk(float* __restrict__ out, int b, int4 r, int lc,
                 const float4& lo, const float4& hi) {
    const int y = r.x, x = r.y, s = r.z, t = r.w;
    const size_t cell0 = (((size_t)b * HH + y) * WW + x) * TT + t;
    float* d = out + cell0 * CELL_F + (size_t)lc * 8;
    if (s == 1) {
        stg256_cs(d, lo, hi);
    } else {
        const size_t dX = (size_t)TT * CELL_F;        // +1 in x (in floats)
        const size_t dY = (size_t)WW * TT * CELL_F;   // +1 in y
        stg256_cs(d,           lo, hi);
        stg256_cs(d + dX,      lo, hi);
        stg256_cs(d + dY,      lo, hi);
        stg256_cs(d + dY + dX, lo, hi);
    }
}

// Two contiguous patches per block. Their payloads form one linear 18432B
// range in tok, copied as 192 threads x 3 x 32B chunks with 256-bit accesses
// (all 6 loads front-batched -> max per-warp MLP). The chunk->patch boundary
// (chunk 288) falls on a warp boundary, so no intra-warp divergence:
// k=0 chunks are all patch A, k=2 all patch B, k=1 splits at thread 96.
// The position tiling partitions the grid, so every output cell is written
// exactly once per launch (deterministic across graph replays).
__global__ __launch_bounds__(THREADS, 7)
void apt_expand_kernel(const float* __restrict__ tok,
                       const int*   __restrict__ positions,
                       float*       __restrict__ out,
                       int P) {
    const int i0 = blockIdx.x * 2;
    const int i1 = i0 + 1;
    const int tix = threadIdx.x;

    const int4 ra = __ldg((const int4*)(positions + (size_t)i0 * 4));
    const int4 rb = __ldg((const int4*)(positions + (size_t)i1 * 4));

    // Front-batch all 3 256-bit loads over the pair's contiguous payload
    const float* src = tok + (size_t)i0 * CELL_F;
    float4 lo0, hi0, lo1, hi1, lo2, hi2;
    ldg256_cs(src + (size_t)(tix            ) * 8, lo0, hi0);
    ldg256_cs(src + (size_t)(tix +     THREADS) * 8, lo1, hi1);
    ldg256_cs(src + (size_t)(tix + 2 * THREADS) * 8, lo2, hi2);

    const int bA = i0 / P;
    const int bB = i1 / P;

    // k=0: chunks 0..191 -> patch A
    store_chunk(out, bA, ra, tix, lo0, hi0);

    // k=1: chunks 192..383 -> A for tix<96 (chunk<288), else B (warp-aligned)
    {
        const int c = tix + THREADS;
        if (c < CELL_C) store_chunk(out, bA, ra, c, lo1, hi1);
        else            store_chunk(out, bB, rb, c - CELL_C, lo1, hi1);
    }

    // k=2: chunks 384..575 -> patch B
    store_chunk(out, bB, rb, tix + 2 * THREADS - CELL_C, lo2, hi2);
}

extern "C" void kernel_launch(void* const* d_in, const int* in_sizes, int n_in,
                              void* d_out, int out_size) {
    const float* tok = (const float*)d_in[0];       // modality_tokens [B, P*BS, D] fp32
    const int*   pos = (const int*)d_in[1];         // positions [B, P, 4] int32

    int P  = in_sizes[1] / (BB * 4);                // 2560
    int BP = BB * P;                                // 20480 patches (even)

    apt_expand_kernel<<<BP / 2, THREADS>>>(tok, pos, (float*)d_out, P);
}